// round 7
// baseline (speedup 1.0000x reference)
#include <cuda_runtime.h>
#include <cuda_bf16.h>
#include <math.h>

// Problem constants (fixed by the dataset)
#define BGRAPHS 1024
#define DDIM    256
#define KDIM    512   // 2*DDIM (q_star width)
#define NGATES  1024  // 4*DDIM
#define NITERS  6

// Static device scratch (no allocations allowed)
__device__ __nv_bfloat16 g_Wh[NGATES * KDIM];        // folded weights hi, n-major [j'][k]
__device__ __nv_bfloat16 g_Wl[NGATES * KDIM];        // folded weights lo (residual)
__device__ float g_bias[NGATES];                     // b_ih + b_hh, gate-interleaved j'=hid*4+gate
__device__ __nv_bfloat16 g_Xh[2][BGRAPHS * KDIM];    // bf16-hi state [h | readout], ping-pong
__device__ __nv_bfloat16 g_Xl[2][BGRAPHS * KDIM];    // bf16-lo residual
__device__ float g_c[BGRAPHS * DDIM];                // LSTM cell state
__device__ int   g_segstart[BGRAPHS + 1];

// ---------------------------------------------------------------------------
// helpers
// ---------------------------------------------------------------------------
__device__ __forceinline__ float fast_sig(float x) {
    return 1.f / (1.f + __expf(-x));
}
__device__ __forceinline__ float fast_tanh(float x) {
    float e2 = __expf(2.f * fabsf(x));
    float t  = 1.f - 2.f / (e2 + 1.f);   // robust for |x| large (e2=inf -> t=1)
    return copysignf(t, x);
}
__device__ __forceinline__ void cp16(unsigned dst, const void* src) {
    asm volatile("cp.async.ca.shared.global [%0], [%1], 16;" :: "r"(dst), "l"(src));
}

// ---------------------------------------------------------------------------
// setup kernels
// ---------------------------------------------------------------------------
__global__ void zero_init() {
    int i = blockIdx.x * blockDim.x + threadIdx.x;   // 524288 threads
    __nv_bfloat16 z = __float2bfloat16(0.f);
    g_Xh[0][i] = z;
    g_Xl[0][i] = z;
    if (i < BGRAPHS * DDIM) g_c[i] = 0.f;
}

// segment_ids sorted ascending -> binary search boundaries
__global__ void seg_bounds(const int* __restrict__ seg, int n) {
    int g = blockIdx.x * blockDim.x + threadIdx.x;
    if (g > BGRAPHS) return;
    int lo = 0, hi = n;
    while (lo < hi) {
        int mid = (lo + hi) >> 1;
        if (seg[mid] < g) lo = mid + 1; else hi = mid;
    }
    g_segstart[g] = lo;
}

// Fold W_ih[:, :256] + W_hh; reorder rows so that the 4 gates of a hidden
// unit are adjacent: j' = hid*4 + gate (original row j = gate*256 + hid,
// pytorch gate order i,f,g,o). Split into bf16 hi + residual lo, stored
// n-major [j'][k] so GEMM B-tiles load coalesced along k.
__global__ void fold_weights(const float* __restrict__ W_ih,
                             const float* __restrict__ W_hh,
                             const float* __restrict__ b_ih,
                             const float* __restrict__ b_hh) {
    int t = blockIdx.x;          // j' = 0..1023
    int k = threadIdx.x;         // 0..511
    int hid = t >> 2, gate = t & 3;
    int j = gate * DDIM + hid;
    float w = W_ih[j * KDIM + k];
    if (k < DDIM) w += W_hh[j * DDIM + k];
    __nv_bfloat16 wh = __float2bfloat16(w);
    __nv_bfloat16 wl = __float2bfloat16(w - __bfloat162float(wh));
    g_Wh[t * KDIM + k] = wh;
    g_Wl[t * KDIM + k] = wl;
    if (k == 0) g_bias[t] = b_ih[j] + b_hh[j];
}

// ---------------------------------------------------------------------------
// LSTM step on tensor cores: gates = x @ W' with bf16x3 emulated fp32
// (Ah*Bh + Ah*Bl + Al*Bh, fp32 accumulate). A is PRE-SPLIT bf16 (written by
// the producers), so the mainloop is pure cp.async + mma. CTA 128x64,
// 8 warps (4m x 2n), warp tile 32x32 via mma.m16n8k16, double-buffered
// K=16 stages. Smem row stride 24 bf16 = 48B: 16B-aligned for cp.async and
// conflict-free for fragment loads ((12*qr+qc) mod 32 covers all banks).
// Gate-interleaved columns -> register-local LSTM epilogue via shfl.
// ---------------------------------------------------------------------------
#define SMN 24
#define NSTG 32   // 512 / 16

#define MMA816(d, a, b) \
    asm volatile("mma.sync.aligned.m16n8k16.row.col.f32.bf16.bf16.f32 " \
                 "{%0,%1,%2,%3},{%4,%5,%6,%7},{%8,%9},{%0,%1,%2,%3};" \
                 : "+f"((d)[0]), "+f"((d)[1]), "+f"((d)[2]), "+f"((d)[3]) \
                 : "r"((a)[0]), "r"((a)[1]), "r"((a)[2]), "r"((a)[3]), \
                   "r"((b)[0]), "r"((b)[1]))

__global__ void __launch_bounds__(256) lstm_mma(float* __restrict__ hf, int it) {
    const __nv_bfloat16* xh = g_Xh[it & 1];
    const __nv_bfloat16* xl = g_Xl[it & 1];
    __nv_bfloat16* yh = g_Xh[(it + 1) & 1];
    __nv_bfloat16* yl = g_Xl[(it + 1) & 1];

    __shared__ __align__(16) __nv_bfloat16 Ah[2][128][SMN], Al[2][128][SMN];
    __shared__ __align__(16) __nv_bfloat16 Bh[2][64][SMN],  Bl[2][64][SMN];

    int tid  = threadIdx.x;
    int lane = tid & 31, wid = tid >> 5;
    int qr = lane >> 2, qc = lane & 3;
    int wm = (wid & 3) * 32, wn = (wid >> 2) * 32;
    int m0 = blockIdx.y * 128, n0 = blockIdx.x * 64;

    // cp.async mapping: 3 x 16B per thread per stage
    int arow = tid >> 1, ac8 = (tid & 1) * 8;          // A: 128 rows x 2 chunks
    int t2 = tid & 127;
    int brow = t2 >> 1, bc8 = (t2 & 1) * 8;            // B: 64 rows x 2 chunks
    const __nv_bfloat16* wsrc = (tid < 128) ? g_Wh : g_Wl;

    unsigned dAh[2], dAl[2], dB[2];
#pragma unroll
    for (int b = 0; b < 2; b++) {
        dAh[b] = (unsigned)__cvta_generic_to_shared(&Ah[b][arow][ac8]);
        dAl[b] = (unsigned)__cvta_generic_to_shared(&Al[b][arow][ac8]);
        dB[b]  = (unsigned)__cvta_generic_to_shared(
                     (tid < 128) ? &Bh[b][brow][bc8] : &Bl[b][brow][bc8]);
    }
    const __nv_bfloat16* asrc_h = xh + (size_t)(m0 + arow) * KDIM + ac8;
    const __nv_bfloat16* asrc_l = xl + (size_t)(m0 + arow) * KDIM + ac8;
    const __nv_bfloat16* bsrc   = wsrc + (size_t)(n0 + brow) * KDIM + bc8;

    float acc[2][4][4];
#pragma unroll
    for (int mb = 0; mb < 2; mb++)
#pragma unroll
        for (int nb = 0; nb < 4; nb++)
#pragma unroll
            for (int j = 0; j < 4; j++) acc[mb][nb][j] = 0.f;

#define ISSUE(s, buf) do { \
    cp16(dAh[buf], asrc_h + (s) * 16); \
    cp16(dAl[buf], asrc_l + (s) * 16); \
    cp16(dB[buf],  bsrc   + (s) * 16); \
    asm volatile("cp.async.commit_group;"); \
} while (0)

#define COMPUTE(buf) do { \
    unsigned ah[2][4], al[2][4], bh[4][2], bl[4][2]; \
    _Pragma("unroll") \
    for (int mb = 0; mb < 2; mb++) { \
        const __nv_bfloat16* ph = &Ah[buf][wm + mb*16 + qr][qc*2]; \
        ah[mb][0] = *(const unsigned*)ph; \
        ah[mb][1] = *(const unsigned*)(ph + 8*SMN); \
        ah[mb][2] = *(const unsigned*)(ph + 8); \
        ah[mb][3] = *(const unsigned*)(ph + 8*SMN + 8); \
        const __nv_bfloat16* pl = &Al[buf][wm + mb*16 + qr][qc*2]; \
        al[mb][0] = *(const unsigned*)pl; \
        al[mb][1] = *(const unsigned*)(pl + 8*SMN); \
        al[mb][2] = *(const unsigned*)(pl + 8); \
        al[mb][3] = *(const unsigned*)(pl + 8*SMN + 8); \
    } \
    _Pragma("unroll") \
    for (int nb = 0; nb < 4; nb++) { \
        const __nv_bfloat16* ph = &Bh[buf][wn + nb*8 + qr][qc*2]; \
        bh[nb][0] = *(const unsigned*)ph; \
        bh[nb][1] = *(const unsigned*)(ph + 8); \
        const __nv_bfloat16* pl = &Bl[buf][wn + nb*8 + qr][qc*2]; \
        bl[nb][0] = *(const unsigned*)pl; \
        bl[nb][1] = *(const unsigned*)(pl + 8); \
    } \
    _Pragma("unroll") \
    for (int mb = 0; mb < 2; mb++) \
    _Pragma("unroll") \
    for (int nb = 0; nb < 4; nb++) { \
        MMA816(acc[mb][nb], ah[mb], bh[nb]); \
        MMA816(acc[mb][nb], ah[mb], bl[nb]); \
        MMA816(acc[mb][nb], al[mb], bh[nb]); \
    } \
} while (0)

    ISSUE(0, 0);
    for (int s = 0; s < NSTG; s++) {
        if (s < NSTG - 1) {
            ISSUE(s + 1, (s + 1) & 1);
            asm volatile("cp.async.wait_group 1;");
        } else {
            asm volatile("cp.async.wait_group 0;");
        }
        __syncthreads();
        COMPUTE(s & 1);
        __syncthreads();   // protect buffer (s&1) before it is re-filled at s+1
    }

    // Epilogue: even-qc lane holds (gi,gf), lane+1 holds (gg,go) of same hid.
#pragma unroll
    for (int mb = 0; mb < 2; mb++)
#pragma unroll
    for (int nb = 0; nb < 4; nb++) {
        float pg0 = __shfl_down_sync(0xffffffffu, acc[mb][nb][0], 1);
        float pg1 = __shfl_down_sync(0xffffffffu, acc[mb][nb][1], 1);
        float pg2 = __shfl_down_sync(0xffffffffu, acc[mb][nb][2], 1);
        float pg3 = __shfl_down_sync(0xffffffffu, acc[mb][nb][3], 1);
        if (!(qc & 1)) {
            int hid = ((n0 + wn) >> 2) + nb * 2 + (qc >> 1);
            float4 bb = *(const float4*)&g_bias[hid * 4];
            int g0 = m0 + wm + mb * 16 + qr;
            {
                float gi = acc[mb][nb][0] + bb.x, gf = acc[mb][nb][1] + bb.y;
                float gg = pg0 + bb.z,            go = pg1 + bb.w;
                float cold = g_c[g0 * DDIM + hid];
                float cn = fast_sig(gf) * cold + fast_sig(gi) * fast_tanh(gg);
                float hn = fast_sig(go) * fast_tanh(cn);
                g_c[g0 * DDIM + hid] = cn;
                hf[g0 * KDIM + hid]  = hn;                    // fp32 h (attn + output)
                __nv_bfloat16 hh = __float2bfloat16(hn);
                yh[g0 * KDIM + hid] = hh;                     // pre-split for next GEMM
                yl[g0 * KDIM + hid] = __float2bfloat16(hn - __bfloat162float(hh));
            }
            {
                int g1 = g0 + 8;
                float gi = acc[mb][nb][2] + bb.x, gf = acc[mb][nb][3] + bb.y;
                float gg = pg2 + bb.z,            go = pg3 + bb.w;
                float cold = g_c[g1 * DDIM + hid];
                float cn = fast_sig(gf) * cold + fast_sig(gi) * fast_tanh(gg);
                float hn = fast_sig(go) * fast_tanh(cn);
                g_c[g1 * DDIM + hid] = cn;
                hf[g1 * KDIM + hid]  = hn;
                __nv_bfloat16 hh = __float2bfloat16(hn);
                yh[g1 * KDIM + hid] = hh;
                yl[g1 * KDIM + hid] = __float2bfloat16(hn - __bfloat162float(hh));
            }
        }
    }
}

// ---------------------------------------------------------------------------
// Fused attention + readout, single pass over feat via BRANCHLESS online
// softmax with a running weighted vector, depth-1 prefetch (MLP=2/warp).
// One block per graph (segments sorted); warp states merged in shared.
// Writes readout fp32 into xf[:,256:512] and bf16 hi/lo into next state buf.
// ---------------------------------------------------------------------------
__global__ void __launch_bounds__(256) attn_pass(const float* __restrict__ feat,
                                                 float* __restrict__ xf, int it) {
    __nv_bfloat16* yh = g_Xh[(it + 1) & 1];
    __nv_bfloat16* yl = g_Xl[(it + 1) & 1];

    int g    = blockIdx.x;
    int t    = threadIdx.x;
    int wid  = t >> 5;
    int lane = t & 31;

    const float* q = xf + g * KDIM;                // q = h just written by lstm_mma
    float4 qa = *(const float4*)&q[lane * 4];
    float4 qb = *(const float4*)&q[128 + lane * 4];

    int ns = g_segstart[g], ne = g_segstart[g + 1];

    float m = -INFINITY, s = 0.f;
    float4 va = make_float4(0.f, 0.f, 0.f, 0.f);
    float4 vb = make_float4(0.f, 0.f, 0.f, 0.f);

    int n = ns + wid;
    float4 c1 = make_float4(0.f, 0.f, 0.f, 0.f);
    float4 c2 = make_float4(0.f, 0.f, 0.f, 0.f);
    if (n < ne) {
        const float* f = feat + (size_t)n * DDIM;
        c1 = *(const float4*)&f[lane * 4];
        c2 = *(const float4*)&f[128 + lane * 4];
    }
    while (n < ne) {
        int n2 = n + 8;
        float4 p1 = make_float4(0.f, 0.f, 0.f, 0.f);
        float4 p2 = make_float4(0.f, 0.f, 0.f, 0.f);
        if (n2 < ne) {                              // prefetch next node
            const float* f = feat + (size_t)n2 * DDIM;
            p1 = *(const float4*)&f[lane * 4];
            p2 = *(const float4*)&f[128 + lane * 4];
        }
        float e = c1.x * qa.x;
        e = fmaf(c1.y, qa.y, e); e = fmaf(c1.z, qa.z, e); e = fmaf(c1.w, qa.w, e);
        e = fmaf(c2.x, qb.x, e); e = fmaf(c2.y, qb.y, e);
        e = fmaf(c2.z, qb.z, e); e = fmaf(c2.w, qb.w, e);
        e += __shfl_xor_sync(0xffffffffu, e, 16);
        e += __shfl_xor_sync(0xffffffffu, e, 8);
        e += __shfl_xor_sync(0xffffffffu, e, 4);
        e += __shfl_xor_sync(0xffffffffu, e, 2);
        e += __shfl_xor_sync(0xffffffffu, e, 1);
        // branchless online-softmax update (exp(-inf)=0 covers first node)
        float mn = fmaxf(m, e);
        float sc = __expf(m - mn);
        float w  = __expf(e - mn);
        s = fmaf(s, sc, w);
        va.x = fmaf(va.x, sc, w * c1.x); va.y = fmaf(va.y, sc, w * c1.y);
        va.z = fmaf(va.z, sc, w * c1.z); va.w = fmaf(va.w, sc, w * c1.w);
        vb.x = fmaf(vb.x, sc, w * c2.x); vb.y = fmaf(vb.y, sc, w * c2.y);
        vb.z = fmaf(vb.z, sc, w * c2.z); vb.w = fmaf(vb.w, sc, w * c2.w);
        m = mn;
        c1 = p1; c2 = p2;
        n = n2;
    }

    __shared__ float sm_m[8], sm_s[8];
    __shared__ float sm_v[8][256];
    if (lane == 0) { sm_m[wid] = m; sm_s[wid] = s; }
    *(float4*)&sm_v[wid][lane * 4]       = va;
    *(float4*)&sm_v[wid][128 + lane * 4] = vb;
    __syncthreads();

    // each thread finalizes one output dim
    float M = sm_m[0];
#pragma unroll
    for (int w = 1; w < 8; w++) M = fmaxf(M, sm_m[w]);
    float S = 0.f, val = 0.f;
#pragma unroll
    for (int w = 0; w < 8; w++) {
        float fw = (sm_s[w] > 0.f) ? __expf(sm_m[w] - M) : 0.f;  // guard empty warps
        S = fmaf(sm_s[w], fw, S);
        val = fmaf(sm_v[w][t], fw, val);
    }
    float r = (S > 0.f) ? val / S : 0.f;            // empty graph -> 0
    xf[g * KDIM + DDIM + t] = r;                    // fp32 (output at it=5)
    __nv_bfloat16 rh = __float2bfloat16(r);
    yh[g * KDIM + DDIM + t] = rh;                   // pre-split for next GEMM
    yl[g * KDIM + DDIM + t] = __float2bfloat16(r - __bfloat162float(rh));
}

// ---------------------------------------------------------------------------
// launch
// ---------------------------------------------------------------------------
extern "C" void kernel_launch(void* const* d_in, const int* in_sizes, int n_in,
                              void* d_out, int out_size) {
    const float* feat = (const float*)d_in[0];
    const float* W_ih = (const float*)d_in[1];
    const float* W_hh = (const float*)d_in[2];
    const float* b_ih = (const float*)d_in[3];
    const float* b_hh = (const float*)d_in[4];
    const int*   seg  = (const int*)d_in[5];
    int N = in_sizes[0] / DDIM;

    float* out = (float*)d_out;   // fp32 state buffer: layout == [h | readout] == q_star

    zero_init<<<1024, 512>>>();
    seg_bounds<<<9, 128>>>(seg, N);
    fold_weights<<<NGATES, KDIM>>>(W_ih, W_hh, b_ih, b_hh);

    for (int it = 0; it < NITERS; it++) {
        lstm_mma<<<dim3(16, 8), 256>>>(out, it);
        attn_pass<<<BGRAPHS, 256>>>(feat, out, it);
    }
    // After it=5, out holds [h6 | readout6] = q_star.
}

// round 8
// speedup vs baseline: 1.0250x; 1.0250x over previous
#include <cuda_runtime.h>
#include <cuda_bf16.h>
#include <math.h>

// Problem constants (fixed by the dataset)
#define BGRAPHS 1024
#define DDIM    256
#define KDIM    512   // 2*DDIM (q_star width)
#define NGATES  1024  // 4*DDIM
#define NITERS  6

// Static device scratch (no allocations allowed)
__device__ __nv_bfloat16 g_Wh[NGATES * KDIM];        // folded weights hi, n-major [j'][k]
__device__ __nv_bfloat16 g_Wl[NGATES * KDIM];        // folded weights lo (residual)
__device__ float g_bias[NGATES];                     // b_ih + b_hh, gate-interleaved j'=hid*4+gate
__device__ __nv_bfloat16 g_Xh[2][BGRAPHS * KDIM];    // bf16-hi state [h | readout], ping-pong
__device__ __nv_bfloat16 g_Xl[2][BGRAPHS * KDIM];    // bf16-lo residual
__device__ float g_c[BGRAPHS * DDIM];                // LSTM cell state
__device__ int   g_segstart[BGRAPHS + 1];

// ---------------------------------------------------------------------------
// helpers
// ---------------------------------------------------------------------------
__device__ __forceinline__ float fast_sig(float x) {
    return 1.f / (1.f + __expf(-x));
}
__device__ __forceinline__ float fast_tanh(float x) {
    float e2 = __expf(2.f * fabsf(x));
    float t  = 1.f - 2.f / (e2 + 1.f);   // robust for |x| large (e2=inf -> t=1)
    return copysignf(t, x);
}
__device__ __forceinline__ void cp16(unsigned dst, const void* src) {
    asm volatile("cp.async.ca.shared.global [%0], [%1], 16;" :: "r"(dst), "l"(src));
}

// ---------------------------------------------------------------------------
// setup kernels
// ---------------------------------------------------------------------------
__global__ void zero_init() {
    int i = blockIdx.x * blockDim.x + threadIdx.x;   // 524288 threads
    __nv_bfloat16 z = __float2bfloat16(0.f);
    g_Xh[0][i] = z;
    g_Xl[0][i] = z;
    if (i < BGRAPHS * DDIM) g_c[i] = 0.f;
}

// segment_ids sorted ascending -> binary search boundaries
__global__ void seg_bounds(const int* __restrict__ seg, int n) {
    int g = blockIdx.x * blockDim.x + threadIdx.x;
    if (g > BGRAPHS) return;
    int lo = 0, hi = n;
    while (lo < hi) {
        int mid = (lo + hi) >> 1;
        if (seg[mid] < g) lo = mid + 1; else hi = mid;
    }
    g_segstart[g] = lo;
}

// Fold W_ih[:, :256] + W_hh; reorder rows so that the 4 gates of a hidden
// unit are adjacent: j' = hid*4 + gate (original row j = gate*256 + hid,
// pytorch gate order i,f,g,o). Split into bf16 hi + residual lo, stored
// n-major [j'][k] so GEMM B-tiles load coalesced along k.
__global__ void fold_weights(const float* __restrict__ W_ih,
                             const float* __restrict__ W_hh,
                             const float* __restrict__ b_ih,
                             const float* __restrict__ b_hh) {
    int t = blockIdx.x;          // j' = 0..1023
    int k = threadIdx.x;         // 0..511
    int hid = t >> 2, gate = t & 3;
    int j = gate * DDIM + hid;
    float w = W_ih[j * KDIM + k];
    if (k < DDIM) w += W_hh[j * DDIM + k];
    __nv_bfloat16 wh = __float2bfloat16(w);
    __nv_bfloat16 wl = __float2bfloat16(w - __bfloat162float(wh));
    g_Wh[t * KDIM + k] = wh;
    g_Wl[t * KDIM + k] = wl;
    if (k == 0) g_bias[t] = b_ih[j] + b_hh[j];
}

// ---------------------------------------------------------------------------
// LSTM step on tensor cores: gates = x @ W' with bf16x3 emulated fp32
// (Ah*Bh + Ah*Bl + Al*Bh, fp32 accumulate). A is PRE-SPLIT bf16 (producers
// write hi/lo), so the mainloop is pure cp.async + mma.
// CTA 128x64, 8 warps (4m x 2n), warp tile 32x32 via mma.m16n8k16.
// 3-STAGE cp.async ring, BK=32, ONE __syncthreads per stage, prefetch
// depth 2 stages. Smem row stride 40 bf16 = 80B (16B aligned for cp.async).
// Dynamic smem: 3 stages x 30720B = 92160B.
// Gate-interleaved columns -> register-local LSTM epilogue via shfl.
// ---------------------------------------------------------------------------
#define SMN 40
#define BK 32
#define NSTG 16                      // 512 / 32
#define OFF_AL 10240                 // 128*40*2
#define OFF_BH 20480
#define OFF_BL 25600                 // +64*40*2
#define STG_BYTES 30720

#define MMA816(d, a, b) \
    asm volatile("mma.sync.aligned.m16n8k16.row.col.f32.bf16.bf16.f32 " \
                 "{%0,%1,%2,%3},{%4,%5,%6,%7},{%8,%9},{%0,%1,%2,%3};" \
                 : "+f"((d)[0]), "+f"((d)[1]), "+f"((d)[2]), "+f"((d)[3]) \
                 : "r"((a)[0]), "r"((a)[1]), "r"((a)[2]), "r"((a)[3]), \
                   "r"((b)[0]), "r"((b)[1]))

__device__ __forceinline__ void compute_stage(const char* base, int wm, int wn,
                                              int qr, int qc, float acc[2][4][4]) {
    const __nv_bfloat16* Ah = (const __nv_bfloat16*)base;
    const __nv_bfloat16* Al = (const __nv_bfloat16*)(base + OFF_AL);
    const __nv_bfloat16* Bh = (const __nv_bfloat16*)(base + OFF_BH);
    const __nv_bfloat16* Bl = (const __nv_bfloat16*)(base + OFF_BL);
#pragma unroll
    for (int kk = 0; kk < BK; kk += 16) {
        unsigned ah[2][4], al[2][4], bh[4][2], bl[4][2];
#pragma unroll
        for (int mb = 0; mb < 2; mb++) {
            const __nv_bfloat16* ph = Ah + (wm + mb*16 + qr) * SMN + kk + qc*2;
            ah[mb][0] = *(const unsigned*)ph;
            ah[mb][1] = *(const unsigned*)(ph + 8*SMN);
            ah[mb][2] = *(const unsigned*)(ph + 8);
            ah[mb][3] = *(const unsigned*)(ph + 8*SMN + 8);
            const __nv_bfloat16* pl = Al + (wm + mb*16 + qr) * SMN + kk + qc*2;
            al[mb][0] = *(const unsigned*)pl;
            al[mb][1] = *(const unsigned*)(pl + 8*SMN);
            al[mb][2] = *(const unsigned*)(pl + 8);
            al[mb][3] = *(const unsigned*)(pl + 8*SMN + 8);
        }
#pragma unroll
        for (int nb = 0; nb < 4; nb++) {
            const __nv_bfloat16* ph = Bh + (wn + nb*8 + qr) * SMN + kk + qc*2;
            bh[nb][0] = *(const unsigned*)ph;
            bh[nb][1] = *(const unsigned*)(ph + 8);
            const __nv_bfloat16* pl = Bl + (wn + nb*8 + qr) * SMN + kk + qc*2;
            bl[nb][0] = *(const unsigned*)pl;
            bl[nb][1] = *(const unsigned*)(pl + 8);
        }
#pragma unroll
        for (int mb = 0; mb < 2; mb++)
#pragma unroll
        for (int nb = 0; nb < 4; nb++) {
            MMA816(acc[mb][nb], ah[mb], bh[nb]);
            MMA816(acc[mb][nb], ah[mb], bl[nb]);
            MMA816(acc[mb][nb], al[mb], bh[nb]);
        }
    }
}

__global__ void __launch_bounds__(256) lstm_mma(float* __restrict__ hf, int it) {
    extern __shared__ __align__(16) char dynsm[];

    const __nv_bfloat16* xh = g_Xh[it & 1];
    const __nv_bfloat16* xl = g_Xl[it & 1];
    __nv_bfloat16* yh = g_Xh[(it + 1) & 1];
    __nv_bfloat16* yl = g_Xl[(it + 1) & 1];

    int tid  = threadIdx.x;
    int lane = tid & 31, wid = tid >> 5;
    int qr = lane >> 2, qc = lane & 3;
    int wm = (wid & 3) * 32, wn = (wid >> 2) * 32;
    int m0 = blockIdx.y * 128, n0 = blockIdx.x * 64;

    // cp.async mapping: 6 x 16B per thread per stage (Ah x2, Al x2, B x2)
    int arow = tid >> 1, acol = (tid & 1) * 16;        // A: 128 rows x 2 half-rows
    int t2 = tid & 127;
    int brow = t2 >> 1, bcol = (t2 & 1) * 16;          // B: 64 rows x 2 half-rows
    int boff = (tid < 128) ? OFF_BH : OFF_BL;
    const __nv_bfloat16* wsrc = (tid < 128) ? g_Wh : g_Wl;

    unsigned dAh[3], dAl[3], dB[3];
#pragma unroll
    for (int st = 0; st < 3; st++) {
        char* base = dynsm + st * STG_BYTES;
        dAh[st] = (unsigned)__cvta_generic_to_shared(base + (arow * SMN + acol) * 2);
        dAl[st] = (unsigned)__cvta_generic_to_shared(base + OFF_AL + (arow * SMN + acol) * 2);
        dB[st]  = (unsigned)__cvta_generic_to_shared(base + boff + (brow * SMN + bcol) * 2);
    }
    const __nv_bfloat16* asrc_h = xh + (size_t)(m0 + arow) * KDIM + acol;
    const __nv_bfloat16* asrc_l = xl + (size_t)(m0 + arow) * KDIM + acol;
    const __nv_bfloat16* bsrc   = wsrc + (size_t)(n0 + brow) * KDIM + bcol;

    float acc[2][4][4];
#pragma unroll
    for (int mb = 0; mb < 2; mb++)
#pragma unroll
        for (int nb = 0; nb < 4; nb++)
#pragma unroll
            for (int j = 0; j < 4; j++) acc[mb][nb][j] = 0.f;

#define ISSUE(s, st) do { \
    cp16(dAh[st],      asrc_h + (s) * BK); \
    cp16(dAh[st] + 16, asrc_h + (s) * BK + 8); \
    cp16(dAl[st],      asrc_l + (s) * BK); \
    cp16(dAl[st] + 16, asrc_l + (s) * BK + 8); \
    cp16(dB[st],       bsrc   + (s) * BK); \
    cp16(dB[st]  + 16, bsrc   + (s) * BK + 8); \
    asm volatile("cp.async.commit_group;"); \
} while (0)

    ISSUE(0, 0);
    ISSUE(1, 1);

    int st = 0;  // stage buffer index for s
    for (int s = 0; s < NSTG; s++) {
        if (s < NSTG - 1) asm volatile("cp.async.wait_group 1;");
        else              asm volatile("cp.async.wait_group 0;");
        __syncthreads();   // data for stage s visible to all; buffer (s+2)%3 free
        if (s + 2 < NSTG) {
            int st2 = st + 2; if (st2 >= 3) st2 -= 3;
            ISSUE(s + 2, st2);
        }
        compute_stage(dynsm + st * STG_BYTES, wm, wn, qr, qc, acc);
        if (++st == 3) st = 0;
    }

    // Epilogue: even-qc lane holds (gi,gf), lane+1 holds (gg,go) of same hid.
#pragma unroll
    for (int mb = 0; mb < 2; mb++)
#pragma unroll
    for (int nb = 0; nb < 4; nb++) {
        float pg0 = __shfl_down_sync(0xffffffffu, acc[mb][nb][0], 1);
        float pg1 = __shfl_down_sync(0xffffffffu, acc[mb][nb][1], 1);
        float pg2 = __shfl_down_sync(0xffffffffu, acc[mb][nb][2], 1);
        float pg3 = __shfl_down_sync(0xffffffffu, acc[mb][nb][3], 1);
        if (!(qc & 1)) {
            int hid = ((n0 + wn) >> 2) + nb * 2 + (qc >> 1);
            float4 bb = *(const float4*)&g_bias[hid * 4];
            int g0 = m0 + wm + mb * 16 + qr;
            {
                float gi = acc[mb][nb][0] + bb.x, gf = acc[mb][nb][1] + bb.y;
                float gg = pg0 + bb.z,            go = pg1 + bb.w;
                float cold = g_c[g0 * DDIM + hid];
                float cn = fast_sig(gf) * cold + fast_sig(gi) * fast_tanh(gg);
                float hn = fast_sig(go) * fast_tanh(cn);
                g_c[g0 * DDIM + hid] = cn;
                hf[g0 * KDIM + hid]  = hn;                    // fp32 h (attn + output)
                __nv_bfloat16 hh = __float2bfloat16(hn);
                yh[g0 * KDIM + hid] = hh;                     // pre-split for next GEMM
                yl[g0 * KDIM + hid] = __float2bfloat16(hn - __bfloat162float(hh));
            }
            {
                int g1 = g0 + 8;
                float gi = acc[mb][nb][2] + bb.x, gf = acc[mb][nb][3] + bb.y;
                float gg = pg2 + bb.z,            go = pg3 + bb.w;
                float cold = g_c[g1 * DDIM + hid];
                float cn = fast_sig(gf) * cold + fast_sig(gi) * fast_tanh(gg);
                float hn = fast_sig(go) * fast_tanh(cn);
                g_c[g1 * DDIM + hid] = cn;
                hf[g1 * KDIM + hid]  = hn;
                __nv_bfloat16 hh = __float2bfloat16(hn);
                yh[g1 * KDIM + hid] = hh;
                yl[g1 * KDIM + hid] = __float2bfloat16(hn - __bfloat162float(hh));
            }
        }
    }
}

// ---------------------------------------------------------------------------
// Fused attention + readout, single pass over feat via BRANCHLESS online
// softmax with a running weighted vector, depth-1 prefetch (MLP=2/warp).
// One block per graph (segments sorted); warp states merged in shared.
// Writes readout fp32 into xf[:,256:512] and bf16 hi/lo into next state buf.
// ---------------------------------------------------------------------------
__global__ void __launch_bounds__(256) attn_pass(const float* __restrict__ feat,
                                                 float* __restrict__ xf, int it) {
    __nv_bfloat16* yh = g_Xh[(it + 1) & 1];
    __nv_bfloat16* yl = g_Xl[(it + 1) & 1];

    int g    = blockIdx.x;
    int t    = threadIdx.x;
    int wid  = t >> 5;
    int lane = t & 31;

    const float* q = xf + g * KDIM;                // q = h just written by lstm_mma
    float4 qa = *(const float4*)&q[lane * 4];
    float4 qb = *(const float4*)&q[128 + lane * 4];

    int ns = g_segstart[g], ne = g_segstart[g + 1];

    float m = -INFINITY, s = 0.f;
    float4 va = make_float4(0.f, 0.f, 0.f, 0.f);
    float4 vb = make_float4(0.f, 0.f, 0.f, 0.f);

    int n = ns + wid;
    float4 c1 = make_float4(0.f, 0.f, 0.f, 0.f);
    float4 c2 = make_float4(0.f, 0.f, 0.f, 0.f);
    if (n < ne) {
        const float* f = feat + (size_t)n * DDIM;
        c1 = *(const float4*)&f[lane * 4];
        c2 = *(const float4*)&f[128 + lane * 4];
    }
    while (n < ne) {
        int n2 = n + 8;
        float4 p1 = make_float4(0.f, 0.f, 0.f, 0.f);
        float4 p2 = make_float4(0.f, 0.f, 0.f, 0.f);
        if (n2 < ne) {                              // prefetch next node
            const float* f = feat + (size_t)n2 * DDIM;
            p1 = *(const float4*)&f[lane * 4];
            p2 = *(const float4*)&f[128 + lane * 4];
        }
        float e = c1.x * qa.x;
        e = fmaf(c1.y, qa.y, e); e = fmaf(c1.z, qa.z, e); e = fmaf(c1.w, qa.w, e);
        e = fmaf(c2.x, qb.x, e); e = fmaf(c2.y, qb.y, e);
        e = fmaf(c2.z, qb.z, e); e = fmaf(c2.w, qb.w, e);
        e += __shfl_xor_sync(0xffffffffu, e, 16);
        e += __shfl_xor_sync(0xffffffffu, e, 8);
        e += __shfl_xor_sync(0xffffffffu, e, 4);
        e += __shfl_xor_sync(0xffffffffu, e, 2);
        e += __shfl_xor_sync(0xffffffffu, e, 1);
        // branchless online-softmax update (exp(-inf)=0 covers first node)
        float mn = fmaxf(m, e);
        float sc = __expf(m - mn);
        float w  = __expf(e - mn);
        s = fmaf(s, sc, w);
        va.x = fmaf(va.x, sc, w * c1.x); va.y = fmaf(va.y, sc, w * c1.y);
        va.z = fmaf(va.z, sc, w * c1.z); va.w = fmaf(va.w, sc, w * c1.w);
        vb.x = fmaf(vb.x, sc, w * c2.x); vb.y = fmaf(vb.y, sc, w * c2.y);
        vb.z = fmaf(vb.z, sc, w * c2.z); vb.w = fmaf(vb.w, sc, w * c2.w);
        m = mn;
        c1 = p1; c2 = p2;
        n = n2;
    }

    __shared__ float sm_m[8], sm_s[8];
    __shared__ float sm_v[8][256];
    if (lane == 0) { sm_m[wid] = m; sm_s[wid] = s; }
    *(float4*)&sm_v[wid][lane * 4]       = va;
    *(float4*)&sm_v[wid][128 + lane * 4] = vb;
    __syncthreads();

    // each thread finalizes one output dim
    float M = sm_m[0];
#pragma unroll
    for (int w = 1; w < 8; w++) M = fmaxf(M, sm_m[w]);
    float S = 0.f, val = 0.f;
#pragma unroll
    for (int w = 0; w < 8; w++) {
        float fw = (sm_s[w] > 0.f) ? __expf(sm_m[w] - M) : 0.f;  // guard empty warps
        S = fmaf(sm_s[w], fw, S);
        val = fmaf(sm_v[w][t], fw, val);
    }
    float r = (S > 0.f) ? val / S : 0.f;            // empty graph -> 0
    xf[g * KDIM + DDIM + t] = r;                    // fp32 (output at it=5)
    __nv_bfloat16 rh = __float2bfloat16(r);
    yh[g * KDIM + DDIM + t] = rh;                   // pre-split for next GEMM
    yl[g * KDIM + DDIM + t] = __float2bfloat16(r - __bfloat162float(rh));
}

// ---------------------------------------------------------------------------
// launch
// ---------------------------------------------------------------------------
extern "C" void kernel_launch(void* const* d_in, const int* in_sizes, int n_in,
                              void* d_out, int out_size) {
    const float* feat = (const float*)d_in[0];
    const float* W_ih = (const float*)d_in[1];
    const float* W_hh = (const float*)d_in[2];
    const float* b_ih = (const float*)d_in[3];
    const float* b_hh = (const float*)d_in[4];
    const int*   seg  = (const int*)d_in[5];
    int N = in_sizes[0] / DDIM;

    float* out = (float*)d_out;   // fp32 state buffer: layout == [h | readout] == q_star

    // opt-in to 90KB dynamic smem (idempotent attribute set, not an allocation)
    cudaFuncSetAttribute(lstm_mma, cudaFuncAttributeMaxDynamicSharedMemorySize,
                         3 * STG_BYTES);

    zero_init<<<1024, 512>>>();
    seg_bounds<<<9, 128>>>(seg, N);
    fold_weights<<<NGATES, KDIM>>>(W_ih, W_hh, b_ih, b_hh);

    for (int it = 0; it < NITERS; it++) {
        lstm_mma<<<dim3(16, 8), 256, 3 * STG_BYTES>>>(out, it);
        attn_pass<<<BGRAPHS, 256>>>(feat, out, it);
    }
    // After it=5, out holds [h6 | readout6] = q_star.
}

// round 11
// speedup vs baseline: 1.0943x; 1.0676x over previous
#include <cuda_runtime.h>
#include <cuda_bf16.h>
#include <math.h>

// Problem constants (fixed by the dataset)
#define BGRAPHS 1024
#define DDIM    256
#define KDIM    512   // 2*DDIM (q_star width)
#define NGATES  1024  // 4*DDIM
#define NITERS  6

// Static device scratch (no allocations allowed)
__device__ __nv_bfloat16 g_Wh[NGATES * KDIM];        // folded weights hi, n-major [j'][k]
__device__ __nv_bfloat16 g_Wl[NGATES * KDIM];        // folded weights lo (residual)
__device__ float g_bias[NGATES];                     // b_ih + b_hh, gate-interleaved j'=hid*4+gate
__device__ __nv_bfloat16 g_Xh[2][BGRAPHS * KDIM];    // bf16-hi state [h | readout], ping-pong
__device__ __nv_bfloat16 g_Xl[2][BGRAPHS * KDIM];    // bf16-lo residual
__device__ float g_c[BGRAPHS * DDIM];                // LSTM cell state
__device__ int   g_segstart[BGRAPHS + 1];

// ---------------------------------------------------------------------------
// helpers
// ---------------------------------------------------------------------------
__device__ __forceinline__ float fast_sig(float x) {
    return 1.f / (1.f + __expf(-x));
}
__device__ __forceinline__ float fast_tanh(float x) {
    float e2 = __expf(2.f * fabsf(x));
    float t  = 1.f - 2.f / (e2 + 1.f);   // robust for |x| large (e2=inf -> t=1)
    return copysignf(t, x);
}
__device__ __forceinline__ void cp16(unsigned dst, const void* src) {
    asm volatile("cp.async.ca.shared.global [%0], [%1], 16;" :: "r"(dst), "l"(src));
}

// ---------------------------------------------------------------------------
// setup kernels
// ---------------------------------------------------------------------------
__global__ void zero_init() {
    int i = blockIdx.x * blockDim.x + threadIdx.x;   // 524288 threads
    __nv_bfloat16 z = __float2bfloat16(0.f);
    g_Xh[0][i] = z;
    g_Xl[0][i] = z;
    if (i < BGRAPHS * DDIM) g_c[i] = 0.f;
}

// segment_ids sorted ascending -> binary search boundaries
__global__ void seg_bounds(const int* __restrict__ seg, int n) {
    int g = blockIdx.x * blockDim.x + threadIdx.x;
    if (g > BGRAPHS) return;
    int lo = 0, hi = n;
    while (lo < hi) {
        int mid = (lo + hi) >> 1;
        if (seg[mid] < g) lo = mid + 1; else hi = mid;
    }
    g_segstart[g] = lo;
}

// Fold W_ih[:, :256] + W_hh; gate-interleaved rows j' = hid*4 + gate
// (original j = gate*256 + hid, pytorch order i,f,g,o). bf16 hi + residual lo,
// n-major [j'][k] so GEMM B-tiles load coalesced along k.
__global__ void fold_weights(const float* __restrict__ W_ih,
                             const float* __restrict__ W_hh,
                             const float* __restrict__ b_ih,
                             const float* __restrict__ b_hh) {
    int t = blockIdx.x;          // j' = 0..1023
    int k = threadIdx.x;         // 0..511
    int hid = t >> 2, gate = t & 3;
    int j = gate * DDIM + hid;
    float w = W_ih[j * KDIM + k];
    if (k < DDIM) w += W_hh[j * DDIM + k];
    __nv_bfloat16 wh = __float2bfloat16(w);
    __nv_bfloat16 wl = __float2bfloat16(w - __bfloat162float(wh));
    g_Wh[t * KDIM + k] = wh;
    g_Wl[t * KDIM + k] = wl;
    if (k == 0) g_bias[t] = b_ih[j] + b_hh[j];
}

// ---------------------------------------------------------------------------
// LSTM step on tensor cores: gates = x @ W' with bf16x3 emulated fp32
// (Ah*Bh + Ah*Bl + Al*Bh, fp32 accumulate). A is PRE-SPLIT bf16 (producers
// write hi/lo), so the mainloop is pure cp.async + mma.
// CTA 64x64, 8 warps (2m x 4n), warp tile 32x16 via mma.m16n8k16.
// grid 16x16 = 256 CTAs -> ~2 CTAs/SM (16 warps/SM) to hide LDS->MMA latency.
// 3-stage cp.async ring, BK=32, one __syncthreads per stage, prefetch depth 2.
// Smem row stride 40 bf16 = 80B; 3 stages x 20480B = 61440B/CTA (2 fit/SM).
// Gate-interleaved columns -> register-local LSTM epilogue via shfl.
// ---------------------------------------------------------------------------
#define SMN 40
#define BK 32
#define NSTG 16                      // 512 / 32
#define OFF_AL 5120                  // 64*40*2
#define OFF_BH 10240
#define OFF_BL 15360
#define STG_BYTES 20480

#define MMA816(d, a, b) \
    asm volatile("mma.sync.aligned.m16n8k16.row.col.f32.bf16.bf16.f32 " \
                 "{%0,%1,%2,%3},{%4,%5,%6,%7},{%8,%9},{%0,%1,%2,%3};" \
                 : "+f"((d)[0]), "+f"((d)[1]), "+f"((d)[2]), "+f"((d)[3]) \
                 : "r"((a)[0]), "r"((a)[1]), "r"((a)[2]), "r"((a)[3]), \
                   "r"((b)[0]), "r"((b)[1]))

__device__ __forceinline__ void compute_stage(const char* base, int wm, int wn,
                                              int qr, int qc, float acc[2][2][4]) {
    const __nv_bfloat16* Ah = (const __nv_bfloat16*)base;
    const __nv_bfloat16* Al = (const __nv_bfloat16*)(base + OFF_AL);
    const __nv_bfloat16* Bh = (const __nv_bfloat16*)(base + OFF_BH);
    const __nv_bfloat16* Bl = (const __nv_bfloat16*)(base + OFF_BL);
#pragma unroll
    for (int kk = 0; kk < BK; kk += 16) {
        unsigned ah[2][4], al[2][4], bh[2][2], bl[2][2];
#pragma unroll
        for (int mb = 0; mb < 2; mb++) {
            const __nv_bfloat16* ph = Ah + (wm + mb*16 + qr) * SMN + kk + qc*2;
            ah[mb][0] = *(const unsigned*)ph;
            ah[mb][1] = *(const unsigned*)(ph + 8*SMN);
            ah[mb][2] = *(const unsigned*)(ph + 8);
            ah[mb][3] = *(const unsigned*)(ph + 8*SMN + 8);
            const __nv_bfloat16* pl = Al + (wm + mb*16 + qr) * SMN + kk + qc*2;
            al[mb][0] = *(const unsigned*)pl;
            al[mb][1] = *(const unsigned*)(pl + 8*SMN);
            al[mb][2] = *(const unsigned*)(pl + 8);
            al[mb][3] = *(const unsigned*)(pl + 8*SMN + 8);
        }
#pragma unroll
        for (int nb = 0; nb < 2; nb++) {
            const __nv_bfloat16* ph = Bh + (wn + nb*8 + qr) * SMN + kk + qc*2;
            bh[nb][0] = *(const unsigned*)ph;
            bh[nb][1] = *(const unsigned*)(ph + 8);
            const __nv_bfloat16* pl = Bl + (wn + nb*8 + qr) * SMN + kk + qc*2;
            bl[nb][0] = *(const unsigned*)pl;
            bl[nb][1] = *(const unsigned*)(pl + 8);
        }
#pragma unroll
        for (int mb = 0; mb < 2; mb++)
#pragma unroll
        for (int nb = 0; nb < 2; nb++) {
            MMA816(acc[mb][nb], ah[mb], bh[nb]);
            MMA816(acc[mb][nb], ah[mb], bl[nb]);
            MMA816(acc[mb][nb], al[mb], bh[nb]);
        }
    }
}

__global__ void __launch_bounds__(256) lstm_mma(float* __restrict__ hf, int it) {
    extern __shared__ __align__(16) char dynsm[];

    const __nv_bfloat16* xh = g_Xh[it & 1];
    const __nv_bfloat16* xl = g_Xl[it & 1];
    __nv_bfloat16* yh = g_Xh[(it + 1) & 1];
    __nv_bfloat16* yl = g_Xl[(it + 1) & 1];

    int tid  = threadIdx.x;
    int lane = tid & 31, wid = tid >> 5;
    int qr = lane >> 2, qc = lane & 3;
    int wm = (wid & 1) * 32, wn = (wid >> 1) * 16;
    int m0 = blockIdx.y * 64, n0 = blockIdx.x * 64;

    // cp.async mapping: 4 x 16B per thread per stage (Ah, Al, Bh, Bl)
    int arow = tid >> 2;                 // 0..63 (shared by A and B tiles)
    int acol = (tid & 3) * 8;            // 0,8,16,24 (bf16 elements)

    unsigned dAh[3], dAl[3], dBh[3], dBl[3];
#pragma unroll
    for (int st = 0; st < 3; st++) {
        char* base = dynsm + st * STG_BYTES;
        unsigned ro = (arow * SMN + acol) * 2;
        dAh[st] = (unsigned)__cvta_generic_to_shared(base + ro);
        dAl[st] = (unsigned)__cvta_generic_to_shared(base + OFF_AL + ro);
        dBh[st] = (unsigned)__cvta_generic_to_shared(base + OFF_BH + ro);
        dBl[st] = (unsigned)__cvta_generic_to_shared(base + OFF_BL + ro);
    }
    const __nv_bfloat16* asrc_h = xh + (size_t)(m0 + arow) * KDIM + acol;
    const __nv_bfloat16* asrc_l = xl + (size_t)(m0 + arow) * KDIM + acol;
    const __nv_bfloat16* bsrc_h = g_Wh + (size_t)(n0 + arow) * KDIM + acol;
    const __nv_bfloat16* bsrc_l = g_Wl + (size_t)(n0 + arow) * KDIM + acol;

    float acc[2][2][4];
#pragma unroll
    for (int mb = 0; mb < 2; mb++)
#pragma unroll
        for (int nb = 0; nb < 2; nb++)
#pragma unroll
            for (int j = 0; j < 4; j++) acc[mb][nb][j] = 0.f;

#define ISSUE(s, st) do { \
    cp16(dAh[st], asrc_h + (s) * BK); \
    cp16(dAl[st], asrc_l + (s) * BK); \
    cp16(dBh[st], bsrc_h + (s) * BK); \
    cp16(dBl[st], bsrc_l + (s) * BK); \
    asm volatile("cp.async.commit_group;"); \
} while (0)

    ISSUE(0, 0);
    ISSUE(1, 1);

    int st = 0;  // stage buffer index for s
    for (int s = 0; s < NSTG; s++) {
        if (s < NSTG - 1) asm volatile("cp.async.wait_group 1;");
        else              asm volatile("cp.async.wait_group 0;");
        __syncthreads();   // data for stage s visible to all; buffer (s+2)%3 free
        if (s + 2 < NSTG) {
            int st2 = st + 2; if (st2 >= 3) st2 -= 3;
            ISSUE(s + 2, st2);
        }
        compute_stage(dynsm + st * STG_BYTES, wm, wn, qr, qc, acc);
        if (++st == 3) st = 0;
    }

    // Epilogue: even-qc lane holds (gi,gf), lane+1 holds (gg,go) of same hid.
#pragma unroll
    for (int mb = 0; mb < 2; mb++)
#pragma unroll
    for (int nb = 0; nb < 2; nb++) {
        float pg0 = __shfl_down_sync(0xffffffffu, acc[mb][nb][0], 1);
        float pg1 = __shfl_down_sync(0xffffffffu, acc[mb][nb][1], 1);
        float pg2 = __shfl_down_sync(0xffffffffu, acc[mb][nb][2], 1);
        float pg3 = __shfl_down_sync(0xffffffffu, acc[mb][nb][3], 1);
        if (!(qc & 1)) {
            int hid = ((n0 + wn) >> 2) + nb * 2 + (qc >> 1);
            float4 bb = *(const float4*)&g_bias[hid * 4];
            int g0 = m0 + wm + mb * 16 + qr;
            {
                float gi = acc[mb][nb][0] + bb.x, gf = acc[mb][nb][1] + bb.y;
                float gg = pg0 + bb.z,            go = pg1 + bb.w;
                float cold = g_c[g0 * DDIM + hid];
                float cn = fast_sig(gf) * cold + fast_sig(gi) * fast_tanh(gg);
                float hn = fast_sig(go) * fast_tanh(cn);
                g_c[g0 * DDIM + hid] = cn;
                hf[g0 * KDIM + hid]  = hn;                    // fp32 h (attn + output)
                __nv_bfloat16 hh = __float2bfloat16(hn);
                yh[g0 * KDIM + hid] = hh;                     // pre-split for next GEMM
                yl[g0 * KDIM + hid] = __float2bfloat16(hn - __bfloat162float(hh));
            }
            {
                int g1 = g0 + 8;
                float gi = acc[mb][nb][2] + bb.x, gf = acc[mb][nb][3] + bb.y;
                float gg = pg2 + bb.z,            go = pg3 + bb.w;
                float cold = g_c[g1 * DDIM + hid];
                float cn = fast_sig(gf) * cold + fast_sig(gi) * fast_tanh(gg);
                float hn = fast_sig(go) * fast_tanh(cn);
                g_c[g1 * DDIM + hid] = cn;
                hf[g1 * KDIM + hid]  = hn;
                __nv_bfloat16 hh = __float2bfloat16(hn);
                yh[g1 * KDIM + hid] = hh;
                yl[g1 * KDIM + hid] = __float2bfloat16(hn - __bfloat162float(hh));
            }
        }
    }
}

// ---------------------------------------------------------------------------
// Fused attention + readout, single pass over feat via BRANCHLESS online
// softmax with a running weighted vector, depth-1 prefetch (MLP=2/warp).
// One block per graph (segments sorted); warp states merged in shared.
// Writes readout fp32 into xf[:,256:512] and bf16 hi/lo into next state buf.
// ---------------------------------------------------------------------------
__global__ void __launch_bounds__(256) attn_pass(const float* __restrict__ feat,
                                                 float* __restrict__ xf, int it) {
    __nv_bfloat16* yh = g_Xh[(it + 1) & 1];
    __nv_bfloat16* yl = g_Xl[(it + 1) & 1];

    int g    = blockIdx.x;
    int t    = threadIdx.x;
    int wid  = t >> 5;
    int lane = t & 31;

    const float* q = xf + g * KDIM;                // q = h just written by lstm_mma
    float4 qa = *(const float4*)&q[lane * 4];
    float4 qb = *(const float4*)&q[128 + lane * 4];

    int ns = g_segstart[g], ne = g_segstart[g + 1];

    float m = -INFINITY, s = 0.f;
    float4 va = make_float4(0.f, 0.f, 0.f, 0.f);
    float4 vb = make_float4(0.f, 0.f, 0.f, 0.f);

    int n = ns + wid;
    float4 c1 = make_float4(0.f, 0.f, 0.f, 0.f);
    float4 c2 = make_float4(0.f, 0.f, 0.f, 0.f);
    if (n < ne) {
        const float* f = feat + (size_t)n * DDIM;
        c1 = *(const float4*)&f[lane * 4];
        c2 = *(const float4*)&f[128 + lane * 4];
    }
    while (n < ne) {
        int n2 = n + 8;
        float4 p1 = make_float4(0.f, 0.f, 0.f, 0.f);
        float4 p2 = make_float4(0.f, 0.f, 0.f, 0.f);
        if (n2 < ne) {                              // prefetch next node
            const float* f = feat + (size_t)n2 * DDIM;
            p1 = *(const float4*)&f[lane * 4];
            p2 = *(const float4*)&f[128 + lane * 4];
        }
        float e = c1.x * qa.x;
        e = fmaf(c1.y, qa.y, e); e = fmaf(c1.z, qa.z, e); e = fmaf(c1.w, qa.w, e);
        e = fmaf(c2.x, qb.x, e); e = fmaf(c2.y, qb.y, e);
        e = fmaf(c2.z, qb.z, e); e = fmaf(c2.w, qb.w, e);
        e += __shfl_xor_sync(0xffffffffu, e, 16);
        e += __shfl_xor_sync(0xffffffffu, e, 8);
        e += __shfl_xor_sync(0xffffffffu, e, 4);
        e += __shfl_xor_sync(0xffffffffu, e, 2);
        e += __shfl_xor_sync(0xffffffffu, e, 1);
        // branchless online-softmax update (exp(-inf)=0 covers first node)
        float mn = fmaxf(m, e);
        float sc = __expf(m - mn);
        float w  = __expf(e - mn);
        s = fmaf(s, sc, w);
        va.x = fmaf(va.x, sc, w * c1.x); va.y = fmaf(va.y, sc, w * c1.y);
        va.z = fmaf(va.z, sc, w * c1.z); va.w = fmaf(va.w, sc, w * c1.w);
        vb.x = fmaf(vb.x, sc, w * c2.x); vb.y = fmaf(vb.y, sc, w * c2.y);
        vb.z = fmaf(vb.z, sc, w * c2.z); vb.w = fmaf(vb.w, sc, w * c2.w);
        m = mn;
        c1 = p1; c2 = p2;
        n = n2;
    }

    __shared__ float sm_m[8], sm_s[8];
    __shared__ float sm_v[8][256];
    if (lane == 0) { sm_m[wid] = m; sm_s[wid] = s; }
    *(float4*)&sm_v[wid][lane * 4]       = va;
    *(float4*)&sm_v[wid][128 + lane * 4] = vb;
    __syncthreads();

    // each thread finalizes one output dim
    float M = sm_m[0];
#pragma unroll
    for (int w = 1; w < 8; w++) M = fmaxf(M, sm_m[w]);
    float S = 0.f, val = 0.f;
#pragma unroll
    for (int w = 0; w < 8; w++) {
        float fw = (sm_s[w] > 0.f) ? __expf(sm_m[w] - M) : 0.f;  // guard empty warps
        S = fmaf(sm_s[w], fw, S);
        val = fmaf(sm_v[w][t], fw, val);
    }
    float r = (S > 0.f) ? val / S : 0.f;            // empty graph -> 0
    xf[g * KDIM + DDIM + t] = r;                    // fp32 (output at it=5)
    __nv_bfloat16 rh = __float2bfloat16(r);
    yh[g * KDIM + DDIM + t] = rh;                   // pre-split for next GEMM
    yl[g * KDIM + DDIM + t] = __float2bfloat16(r - __bfloat162float(rh));
}

// ---------------------------------------------------------------------------
// launch
// ---------------------------------------------------------------------------
extern "C" void kernel_launch(void* const* d_in, const int* in_sizes, int n_in,
                              void* d_out, int out_size) {
    const float* feat = (const float*)d_in[0];
    const float* W_ih = (const float*)d_in[1];
    const float* W_hh = (const float*)d_in[2];
    const float* b_ih = (const float*)d_in[3];
    const float* b_hh = (const float*)d_in[4];
    const int*   seg  = (const int*)d_in[5];
    int N = in_sizes[0] / DDIM;

    float* out = (float*)d_out;   // fp32 state buffer: layout == [h | readout] == q_star

    // opt-in to 60KB dynamic smem (idempotent attribute set, not an allocation)
    cudaFuncSetAttribute(lstm_mma, cudaFuncAttributeMaxDynamicSharedMemorySize,
                         3 * STG_BYTES);

    zero_init<<<1024, 512>>>();
    seg_bounds<<<9, 128>>>(seg, N);
    fold_weights<<<NGATES, KDIM>>>(W_ih, W_hh, b_ih, b_hh);

    for (int it = 0; it < NITERS; it++) {
        lstm_mma<<<dim3(16, 16), 256, 3 * STG_BYTES>>>(out, it);
        attn_pass<<<BGRAPHS, 256>>>(feat, out, it);
    }
    // After it=5, out holds [h6 | readout6] = q_star.
}

// round 12
// speedup vs baseline: 1.1684x; 1.0677x over previous
#include <cuda_runtime.h>
#include <cuda_bf16.h>
#include <math.h>

// Problem constants (fixed by the dataset)
#define BGRAPHS 1024
#define DDIM    256
#define KDIM    512   // 2*DDIM (q_star width)
#define NGATES  1024  // 4*DDIM
#define NITERS  6

// Static device scratch (no allocations allowed)
__device__ __nv_bfloat16 g_Wh[NGATES * KDIM];        // folded weights hi, n-major [j'][k]
__device__ __nv_bfloat16 g_Wl[NGATES * KDIM];        // folded weights lo (residual)
__device__ float g_bias[NGATES];                     // b_ih + b_hh, gate-interleaved j'=hid*4+gate
__device__ __nv_bfloat16 g_Xh[2][BGRAPHS * KDIM];    // bf16-hi state [h | readout], ping-pong
__device__ __nv_bfloat16 g_Xl[2][BGRAPHS * KDIM];    // bf16-lo residual
__device__ float g_c[BGRAPHS * DDIM];                // LSTM cell state
__device__ int   g_segstart[BGRAPHS + 1];

// ---------------------------------------------------------------------------
// helpers
// ---------------------------------------------------------------------------
__device__ __forceinline__ float fast_sig(float x) {
    return 1.f / (1.f + __expf(-x));
}
__device__ __forceinline__ float fast_tanh(float x) {
    float e2 = __expf(2.f * fabsf(x));
    float t  = 1.f - 2.f / (e2 + 1.f);   // robust for |x| large (e2=inf -> t=1)
    return copysignf(t, x);
}
__device__ __forceinline__ void cp16(unsigned dst, const void* src) {
    asm volatile("cp.async.ca.shared.global [%0], [%1], 16;" :: "r"(dst), "l"(src));
}

// ---------------------------------------------------------------------------
// setup kernels
// ---------------------------------------------------------------------------
__global__ void zero_init() {
    int i = blockIdx.x * blockDim.x + threadIdx.x;   // 524288 threads
    __nv_bfloat16 z = __float2bfloat16(0.f);
    g_Xh[0][i] = z;
    g_Xl[0][i] = z;
    if (i < BGRAPHS * DDIM) g_c[i] = 0.f;
}

// segment_ids sorted ascending -> binary search boundaries
__global__ void seg_bounds(const int* __restrict__ seg, int n) {
    int g = blockIdx.x * blockDim.x + threadIdx.x;
    if (g > BGRAPHS) return;
    int lo = 0, hi = n;
    while (lo < hi) {
        int mid = (lo + hi) >> 1;
        if (seg[mid] < g) lo = mid + 1; else hi = mid;
    }
    g_segstart[g] = lo;
}

// Fold W_ih[:, :256] + W_hh; gate-interleaved rows j' = hid*4 + gate
// (original j = gate*256 + hid, pytorch order i,f,g,o). bf16 hi + residual lo,
// n-major [j'][k] so GEMM B-tiles load coalesced along k.
__global__ void fold_weights(const float* __restrict__ W_ih,
                             const float* __restrict__ W_hh,
                             const float* __restrict__ b_ih,
                             const float* __restrict__ b_hh) {
    int t = blockIdx.x;          // j' = 0..1023
    int k = threadIdx.x;         // 0..511
    int hid = t >> 2, gate = t & 3;
    int j = gate * DDIM + hid;
    float w = W_ih[j * KDIM + k];
    if (k < DDIM) w += W_hh[j * DDIM + k];
    __nv_bfloat16 wh = __float2bfloat16(w);
    __nv_bfloat16 wl = __float2bfloat16(w - __bfloat162float(wh));
    g_Wh[t * KDIM + k] = wh;
    g_Wl[t * KDIM + k] = wl;
    if (k == 0) g_bias[t] = b_ih[j] + b_hh[j];
}

// ---------------------------------------------------------------------------
// LSTM step on tensor cores: gates = x @ W' with bf16x3 emulated fp32
// (Ah*Bh + Ah*Bl + Al*Bh, fp32 accumulate). A is PRE-SPLIT bf16 (producers
// write hi/lo), so the mainloop is pure cp.async + ldmatrix + mma.
// CTA 64x64, 8 warps (2m x 4n), warp tile 32x16 via mma.m16n8k16.
// grid 16x16 = 256 CTAs -> 2 CTAs/SM (16 warps/SM).
// Fragment loads via ldmatrix.m8n8.x4 (12 LDSM/warp/stage vs 48 LDS.32).
// 3-stage cp.async ring, BK=32, one __syncthreads per stage, prefetch depth 2.
// Smem row stride 40 bf16 = 80B (rows 16B-aligned; 20r mod 32 word-starts ->
// LDSM phases conflict-free). 3 stages x 20480B = 61440B/CTA.
// Gate-interleaved columns -> register-local LSTM epilogue via shfl.
// ---------------------------------------------------------------------------
#define SMN 40
#define BK 32
#define NSTG 16                      // 512 / 32
#define OFF_AL 5120                  // 64*40*2
#define OFF_BH 10240
#define OFF_BL 15360
#define STG_BYTES 20480

#define MMA816(d, a, b) \
    asm volatile("mma.sync.aligned.m16n8k16.row.col.f32.bf16.bf16.f32 " \
                 "{%0,%1,%2,%3},{%4,%5,%6,%7},{%8,%9},{%0,%1,%2,%3};" \
                 : "+f"((d)[0]), "+f"((d)[1]), "+f"((d)[2]), "+f"((d)[3]) \
                 : "r"((a)[0]), "r"((a)[1]), "r"((a)[2]), "r"((a)[3]), \
                   "r"((b)[0]), "r"((b)[1]))

#define LDSM4(r, addr) \
    asm volatile("ldmatrix.sync.aligned.m8n8.x4.shared.b16 {%0,%1,%2,%3}, [%4];" \
                 : "=r"((r)[0]), "=r"((r)[1]), "=r"((r)[2]), "=r"((r)[3]) \
                 : "r"(addr))

// A-frag LDSM: m0=rows+0/k+0, m1=rows+8/k+0, m2=rows+0/k+8, m3=rows+8/k+8
//   -> r0..r3 == mma a0..a3.  lane addr: row = (lane&7) + ((lane>>3)&1)*8,
//   k-plus = (lane>>4)*8.
// B-frag LDSM over [n][k] rows: m0=n+0/k+0, m1=n+0/k+8, m2=n+8/k+0, m3=n+8/k+8
//   -> {r0,r1} = b0,b1 of nb=0; {r2,r3} = b0,b1 of nb=1.
//   lane addr: n-row = (lane&7) + (lane>>4)*8, k-plus = ((lane>>3)&1)*8.
__device__ __forceinline__ void compute_stage(unsigned sb, unsigned aoff, unsigned boff,
                                              float acc[2][2][4]) {
#pragma unroll
    for (int kk = 0; kk < BK; kk += 16) {
        unsigned ah[2][4], al[2][4], bhv[4], blv[4];
        LDSM4(ah[0], sb + aoff + kk * 2);
        LDSM4(ah[1], sb + aoff + 16 * SMN * 2 + kk * 2);
        LDSM4(al[0], sb + OFF_AL + aoff + kk * 2);
        LDSM4(al[1], sb + OFF_AL + aoff + 16 * SMN * 2 + kk * 2);
        LDSM4(bhv, sb + OFF_BH + boff + kk * 2);
        LDSM4(blv, sb + OFF_BL + boff + kk * 2);
#pragma unroll
        for (int mb = 0; mb < 2; mb++)
#pragma unroll
        for (int nb = 0; nb < 2; nb++) {
            MMA816(acc[mb][nb], ah[mb], &bhv[nb * 2]);
            MMA816(acc[mb][nb], ah[mb], &blv[nb * 2]);
            MMA816(acc[mb][nb], al[mb], &bhv[nb * 2]);
        }
    }
}

__global__ void __launch_bounds__(256) lstm_mma(float* __restrict__ hf, int it) {
    extern __shared__ __align__(16) char dynsm[];

    const __nv_bfloat16* xh = g_Xh[it & 1];
    const __nv_bfloat16* xl = g_Xl[it & 1];
    __nv_bfloat16* yh = g_Xh[(it + 1) & 1];
    __nv_bfloat16* yl = g_Xl[(it + 1) & 1];

    int tid  = threadIdx.x;
    int lane = tid & 31, wid = tid >> 5;
    int qr = lane >> 2, qc = lane & 3;
    int wm = (wid & 1) * 32, wn = (wid >> 1) * 16;
    int m0 = blockIdx.y * 64, n0 = blockIdx.x * 64;

    // ldmatrix per-lane byte offsets (relative to tile base, mb=0 / kk=0)
    unsigned aoff = ((wm + (lane & 7) + ((lane >> 3) & 1) * 8) * SMN + (lane >> 4) * 8) * 2;
    unsigned boff = ((wn + (lane & 7) + (lane >> 4) * 8) * SMN + ((lane >> 3) & 1) * 8) * 2;

    // cp.async mapping: 4 x 16B per thread per stage (Ah, Al, Bh, Bl)
    int arow = tid >> 2;                 // 0..63 (shared by A and B tiles)
    int acol = (tid & 3) * 8;            // 0,8,16,24 (bf16 elements)

    unsigned sbase[3], dAh[3], dAl[3], dBh[3], dBl[3];
#pragma unroll
    for (int st = 0; st < 3; st++) {
        char* base = dynsm + st * STG_BYTES;
        sbase[st] = (unsigned)__cvta_generic_to_shared(base);
        unsigned ro = (arow * SMN + acol) * 2;
        dAh[st] = sbase[st] + ro;
        dAl[st] = sbase[st] + OFF_AL + ro;
        dBh[st] = sbase[st] + OFF_BH + ro;
        dBl[st] = sbase[st] + OFF_BL + ro;
    }
    const __nv_bfloat16* asrc_h = xh + (size_t)(m0 + arow) * KDIM + acol;
    const __nv_bfloat16* asrc_l = xl + (size_t)(m0 + arow) * KDIM + acol;
    const __nv_bfloat16* bsrc_h = g_Wh + (size_t)(n0 + arow) * KDIM + acol;
    const __nv_bfloat16* bsrc_l = g_Wl + (size_t)(n0 + arow) * KDIM + acol;

    float acc[2][2][4];
#pragma unroll
    for (int mb = 0; mb < 2; mb++)
#pragma unroll
        for (int nb = 0; nb < 2; nb++)
#pragma unroll
            for (int j = 0; j < 4; j++) acc[mb][nb][j] = 0.f;

#define ISSUE(s, st) do { \
    cp16(dAh[st], asrc_h + (s) * BK); \
    cp16(dAl[st], asrc_l + (s) * BK); \
    cp16(dBh[st], bsrc_h + (s) * BK); \
    cp16(dBl[st], bsrc_l + (s) * BK); \
    asm volatile("cp.async.commit_group;"); \
} while (0)

    ISSUE(0, 0);
    ISSUE(1, 1);

    int st = 0;  // stage buffer index for s
    for (int s = 0; s < NSTG; s++) {
        if (s < NSTG - 1) asm volatile("cp.async.wait_group 1;");
        else              asm volatile("cp.async.wait_group 0;");
        __syncthreads();   // data for stage s visible to all; buffer (s+2)%3 free
        if (s + 2 < NSTG) {
            int st2 = st + 2; if (st2 >= 3) st2 -= 3;
            ISSUE(s + 2, st2);
        }
        compute_stage(sbase[st], aoff, boff, acc);
        if (++st == 3) st = 0;
    }

    // Epilogue: even-qc lane holds (gi,gf), lane+1 holds (gg,go) of same hid.
#pragma unroll
    for (int mb = 0; mb < 2; mb++)
#pragma unroll
    for (int nb = 0; nb < 2; nb++) {
        float pg0 = __shfl_down_sync(0xffffffffu, acc[mb][nb][0], 1);
        float pg1 = __shfl_down_sync(0xffffffffu, acc[mb][nb][1], 1);
        float pg2 = __shfl_down_sync(0xffffffffu, acc[mb][nb][2], 1);
        float pg3 = __shfl_down_sync(0xffffffffu, acc[mb][nb][3], 1);
        if (!(qc & 1)) {
            int hid = ((n0 + wn) >> 2) + nb * 2 + (qc >> 1);
            float4 bb = *(const float4*)&g_bias[hid * 4];
            int g0 = m0 + wm + mb * 16 + qr;
            {
                float gi = acc[mb][nb][0] + bb.x, gf = acc[mb][nb][1] + bb.y;
                float gg = pg0 + bb.z,            go = pg1 + bb.w;
                float cold = g_c[g0 * DDIM + hid];
                float cn = fast_sig(gf) * cold + fast_sig(gi) * fast_tanh(gg);
                float hn = fast_sig(go) * fast_tanh(cn);
                g_c[g0 * DDIM + hid] = cn;
                hf[g0 * KDIM + hid]  = hn;                    // fp32 h (attn + output)
                __nv_bfloat16 hh = __float2bfloat16(hn);
                yh[g0 * KDIM + hid] = hh;                     // pre-split for next GEMM
                yl[g0 * KDIM + hid] = __float2bfloat16(hn - __bfloat162float(hh));
            }
            {
                int g1 = g0 + 8;
                float gi = acc[mb][nb][2] + bb.x, gf = acc[mb][nb][3] + bb.y;
                float gg = pg2 + bb.z,            go = pg3 + bb.w;
                float cold = g_c[g1 * DDIM + hid];
                float cn = fast_sig(gf) * cold + fast_sig(gi) * fast_tanh(gg);
                float hn = fast_sig(go) * fast_tanh(cn);
                g_c[g1 * DDIM + hid] = cn;
                hf[g1 * KDIM + hid]  = hn;
                __nv_bfloat16 hh = __float2bfloat16(hn);
                yh[g1 * KDIM + hid] = hh;
                yl[g1 * KDIM + hid] = __float2bfloat16(hn - __bfloat162float(hh));
            }
        }
    }
}

// ---------------------------------------------------------------------------
// Fused attention + readout, single pass over feat via BRANCHLESS online
// softmax with a running weighted vector, depth-1 prefetch (MLP=2/warp).
// One block per graph (segments sorted); warp states merged in shared.
// Writes readout fp32 into xf[:,256:512] and bf16 hi/lo into next state buf.
// ---------------------------------------------------------------------------
__global__ void __launch_bounds__(256) attn_pass(const float* __restrict__ feat,
                                                 float* __restrict__ xf, int it) {
    __nv_bfloat16* yh = g_Xh[(it + 1) & 1];
    __nv_bfloat16* yl = g_Xl[(it + 1) & 1];

    int g    = blockIdx.x;
    int t    = threadIdx.x;
    int wid  = t >> 5;
    int lane = t & 31;

    const float* q = xf + g * KDIM;                // q = h just written by lstm_mma
    float4 qa = *(const float4*)&q[lane * 4];
    float4 qb = *(const float4*)&q[128 + lane * 4];

    int ns = g_segstart[g], ne = g_segstart[g + 1];

    float m = -INFINITY, s = 0.f;
    float4 va = make_float4(0.f, 0.f, 0.f, 0.f);
    float4 vb = make_float4(0.f, 0.f, 0.f, 0.f);

    int n = ns + wid;
    float4 c1 = make_float4(0.f, 0.f, 0.f, 0.f);
    float4 c2 = make_float4(0.f, 0.f, 0.f, 0.f);
    if (n < ne) {
        const float* f = feat + (size_t)n * DDIM;
        c1 = *(const float4*)&f[lane * 4];
        c2 = *(const float4*)&f[128 + lane * 4];
    }
    while (n < ne) {
        int n2 = n + 8;
        float4 p1 = make_float4(0.f, 0.f, 0.f, 0.f);
        float4 p2 = make_float4(0.f, 0.f, 0.f, 0.f);
        if (n2 < ne) {                              // prefetch next node
            const float* f = feat + (size_t)n2 * DDIM;
            p1 = *(const float4*)&f[lane * 4];
            p2 = *(const float4*)&f[128 + lane * 4];
        }
        float e = c1.x * qa.x;
        e = fmaf(c1.y, qa.y, e); e = fmaf(c1.z, qa.z, e); e = fmaf(c1.w, qa.w, e);
        e = fmaf(c2.x, qb.x, e); e = fmaf(c2.y, qb.y, e);
        e = fmaf(c2.z, qb.z, e); e = fmaf(c2.w, qb.w, e);
        e += __shfl_xor_sync(0xffffffffu, e, 16);
        e += __shfl_xor_sync(0xffffffffu, e, 8);
        e += __shfl_xor_sync(0xffffffffu, e, 4);
        e += __shfl_xor_sync(0xffffffffu, e, 2);
        e += __shfl_xor_sync(0xffffffffu, e, 1);
        // branchless online-softmax update (exp(-inf)=0 covers first node)
        float mn = fmaxf(m, e);
        float sc = __expf(m - mn);
        float w  = __expf(e - mn);
        s = fmaf(s, sc, w);
        va.x = fmaf(va.x, sc, w * c1.x); va.y = fmaf(va.y, sc, w * c1.y);
        va.z = fmaf(va.z, sc, w * c1.z); va.w = fmaf(va.w, sc, w * c1.w);
        vb.x = fmaf(vb.x, sc, w * c2.x); vb.y = fmaf(vb.y, sc, w * c2.y);
        vb.z = fmaf(vb.z, sc, w * c2.z); vb.w = fmaf(vb.w, sc, w * c2.w);
        m = mn;
        c1 = p1; c2 = p2;
        n = n2;
    }

    __shared__ float sm_m[8], sm_s[8];
    __shared__ float sm_v[8][256];
    if (lane == 0) { sm_m[wid] = m; sm_s[wid] = s; }
    *(float4*)&sm_v[wid][lane * 4]       = va;
    *(float4*)&sm_v[wid][128 + lane * 4] = vb;
    __syncthreads();

    // each thread finalizes one output dim
    float M = sm_m[0];
#pragma unroll
    for (int w = 1; w < 8; w++) M = fmaxf(M, sm_m[w]);
    float S = 0.f, val = 0.f;
#pragma unroll
    for (int w = 0; w < 8; w++) {
        float fw = (sm_s[w] > 0.f) ? __expf(sm_m[w] - M) : 0.f;  // guard empty warps
        S = fmaf(sm_s[w], fw, S);
        val = fmaf(sm_v[w][t], fw, val);
    }
    float r = (S > 0.f) ? val / S : 0.f;            // empty graph -> 0
    xf[g * KDIM + DDIM + t] = r;                    // fp32 (output at it=5)
    __nv_bfloat16 rh = __float2bfloat16(r);
    yh[g * KDIM + DDIM + t] = rh;                   // pre-split for next GEMM
    yl[g * KDIM + DDIM + t] = __float2bfloat16(r - __bfloat162float(rh));
}

// ---------------------------------------------------------------------------
// launch
// ---------------------------------------------------------------------------
extern "C" void kernel_launch(void* const* d_in, const int* in_sizes, int n_in,
                              void* d_out, int out_size) {
    const float* feat = (const float*)d_in[0];
    const float* W_ih = (const float*)d_in[1];
    const float* W_hh = (const float*)d_in[2];
    const float* b_ih = (const float*)d_in[3];
    const float* b_hh = (const float*)d_in[4];
    const int*   seg  = (const int*)d_in[5];
    int N = in_sizes[0] / DDIM;

    float* out = (float*)d_out;   // fp32 state buffer: layout == [h | readout] == q_star

    // opt-in to 60KB dynamic smem (idempotent attribute set, not an allocation)
    cudaFuncSetAttribute(lstm_mma, cudaFuncAttributeMaxDynamicSharedMemorySize,
                         3 * STG_BYTES);

    zero_init<<<1024, 512>>>();
    seg_bounds<<<9, 128>>>(seg, N);
    fold_weights<<<NGATES, KDIM>>>(W_ih, W_hh, b_ih, b_hh);

    for (int it = 0; it < NITERS; it++) {
        lstm_mma<<<dim3(16, 16), 256, 3 * STG_BYTES>>>(out, it);
        attn_pass<<<BGRAPHS, 256>>>(feat, out, it);
    }
    // After it=5, out holds [h6 | readout6] = q_star.
}

// round 13
// speedup vs baseline: 1.1894x; 1.0179x over previous
#include <cuda_runtime.h>
#include <cuda_bf16.h>
#include <math.h>

// Problem constants (fixed by the dataset)
#define BGRAPHS 1024
#define DDIM    256
#define KDIM    512   // 2*DDIM (q_star width)
#define NGATES  1024  // 4*DDIM
#define NITERS  6

// Static device scratch (no allocations allowed)
__device__ __nv_bfloat16 g_Wh[NGATES * KDIM];        // folded weights hi, n-major [j'][k]
__device__ __nv_bfloat16 g_Wl[NGATES * KDIM];        // folded weights lo (residual)
__device__ float g_bias[NGATES];                     // b_ih + b_hh, gate-interleaved j'=hid*4+gate
__device__ __nv_bfloat16 g_Xh[2][BGRAPHS * KDIM];    // bf16-hi state [h | readout], ping-pong
__device__ __nv_bfloat16 g_Xl[2][BGRAPHS * KDIM];    // bf16-lo residual
__device__ float g_c[BGRAPHS * DDIM];                // LSTM cell state
__device__ int   g_segstart[BGRAPHS + 1];

// ---------------------------------------------------------------------------
// helpers
// ---------------------------------------------------------------------------
__device__ __forceinline__ float fast_sig(float x) {
    return 1.f / (1.f + __expf(-x));
}
__device__ __forceinline__ float fast_tanh(float x) {
    float e2 = __expf(2.f * fabsf(x));
    float t  = 1.f - 2.f / (e2 + 1.f);   // robust for |x| large (e2=inf -> t=1)
    return copysignf(t, x);
}
__device__ __forceinline__ void cp16(unsigned dst, const void* src) {
    asm volatile("cp.async.ca.shared.global [%0], [%1], 16;" :: "r"(dst), "l"(src));
}

// ---------------------------------------------------------------------------
// fused setup: fold weights + zero state + segment bounds in ONE launch.
// grid 1024 x 512.
// ---------------------------------------------------------------------------
__global__ void setup_fused(const float* __restrict__ W_ih,
                            const float* __restrict__ W_hh,
                            const float* __restrict__ b_ih,
                            const float* __restrict__ b_hh,
                            const int* __restrict__ seg, int n) {
    int t = blockIdx.x;          // j' = 0..1023
    int k = threadIdx.x;         // 0..511

    // fold W_ih[:, :256] + W_hh; gate-interleaved rows j' = hid*4 + gate
    // (original j = gate*256 + hid, pytorch order i,f,g,o). bf16 hi + lo.
    int hid = t >> 2, gate = t & 3;
    int j = gate * DDIM + hid;
    float w = W_ih[j * KDIM + k];
    if (k < DDIM) w += W_hh[j * DDIM + k];
    __nv_bfloat16 wh = __float2bfloat16(w);
    __nv_bfloat16 wl = __float2bfloat16(w - __bfloat162float(wh));
    g_Wh[t * KDIM + k] = wh;
    g_Wl[t * KDIM + k] = wl;
    if (k == 0) g_bias[t] = b_ih[j] + b_hh[j];

    // zero initial state (524288 threads == BGRAPHS*KDIM)
    int i = t * 512 + k;
    __nv_bfloat16 z = __float2bfloat16(0.f);
    g_Xh[0][i] = z;
    g_Xl[0][i] = z;
    if (i < BGRAPHS * DDIM) g_c[i] = 0.f;

    // segment bounds: first 1025 global threads binary-search sorted seg ids
    if (i <= BGRAPHS) {
        int lo = 0, hi = n;
        while (lo < hi) {
            int mid = (lo + hi) >> 1;
            if (seg[mid] < i) lo = mid + 1; else hi = mid;
        }
        g_segstart[i] = lo;
    }
}

// ---------------------------------------------------------------------------
// LSTM step on tensor cores: gates = x @ W' with bf16x3 emulated fp32
// (Ah*Bh + Ah*Bl + Al*Bh, fp32 accumulate). A is PRE-SPLIT bf16 (producers
// write hi/lo), so the mainloop is pure cp.async + ldmatrix + mma.
// CTA 64x64, 8 warps (2m x 4n), warp tile 32x16 via mma.m16n8k16.
// grid 16x16 = 256 CTAs -> 2 CTAs/SM (16 warps/SM).
// Fragment loads via ldmatrix.m8n8.x4. 3-stage cp.async ring, BK=32,
// one __syncthreads per stage, prefetch depth 2. Near the mma.sync
// throughput ceiling (~1200 MACs/cyc/SM) -- done optimizing this kernel.
// ---------------------------------------------------------------------------
#define SMN 40
#define BK 32
#define NSTG 16                      // 512 / 32
#define OFF_AL 5120                  // 64*40*2
#define OFF_BH 10240
#define OFF_BL 15360
#define STG_BYTES 20480

#define MMA816(d, a, b) \
    asm volatile("mma.sync.aligned.m16n8k16.row.col.f32.bf16.bf16.f32 " \
                 "{%0,%1,%2,%3},{%4,%5,%6,%7},{%8,%9},{%0,%1,%2,%3};" \
                 : "+f"((d)[0]), "+f"((d)[1]), "+f"((d)[2]), "+f"((d)[3]) \
                 : "r"((a)[0]), "r"((a)[1]), "r"((a)[2]), "r"((a)[3]), \
                   "r"((b)[0]), "r"((b)[1]))

#define LDSM4(r, addr) \
    asm volatile("ldmatrix.sync.aligned.m8n8.x4.shared.b16 {%0,%1,%2,%3}, [%4];" \
                 : "=r"((r)[0]), "=r"((r)[1]), "=r"((r)[2]), "=r"((r)[3]) \
                 : "r"(addr))

__device__ __forceinline__ void compute_stage(unsigned sb, unsigned aoff, unsigned boff,
                                              float acc[2][2][4]) {
#pragma unroll
    for (int kk = 0; kk < BK; kk += 16) {
        unsigned ah[2][4], al[2][4], bhv[4], blv[4];
        LDSM4(ah[0], sb + aoff + kk * 2);
        LDSM4(ah[1], sb + aoff + 16 * SMN * 2 + kk * 2);
        LDSM4(al[0], sb + OFF_AL + aoff + kk * 2);
        LDSM4(al[1], sb + OFF_AL + aoff + 16 * SMN * 2 + kk * 2);
        LDSM4(bhv, sb + OFF_BH + boff + kk * 2);
        LDSM4(blv, sb + OFF_BL + boff + kk * 2);
#pragma unroll
        for (int mb = 0; mb < 2; mb++)
#pragma unroll
        for (int nb = 0; nb < 2; nb++) {
            MMA816(acc[mb][nb], ah[mb], &bhv[nb * 2]);
            MMA816(acc[mb][nb], ah[mb], &blv[nb * 2]);
            MMA816(acc[mb][nb], al[mb], &bhv[nb * 2]);
        }
    }
}

__global__ void __launch_bounds__(256) lstm_mma(float* __restrict__ hf, int it) {
    extern __shared__ __align__(16) char dynsm[];

    const __nv_bfloat16* xh = g_Xh[it & 1];
    const __nv_bfloat16* xl = g_Xl[it & 1];
    __nv_bfloat16* yh = g_Xh[(it + 1) & 1];
    __nv_bfloat16* yl = g_Xl[(it + 1) & 1];

    int tid  = threadIdx.x;
    int lane = tid & 31, wid = tid >> 5;
    int qr = lane >> 2, qc = lane & 3;
    int wm = (wid & 1) * 32, wn = (wid >> 1) * 16;
    int m0 = blockIdx.y * 64, n0 = blockIdx.x * 64;

    // ldmatrix per-lane byte offsets (relative to tile base, mb=0 / kk=0)
    unsigned aoff = ((wm + (lane & 7) + ((lane >> 3) & 1) * 8) * SMN + (lane >> 4) * 8) * 2;
    unsigned boff = ((wn + (lane & 7) + (lane >> 4) * 8) * SMN + ((lane >> 3) & 1) * 8) * 2;

    // cp.async mapping: 4 x 16B per thread per stage (Ah, Al, Bh, Bl)
    int arow = tid >> 2;                 // 0..63 (shared by A and B tiles)
    int acol = (tid & 3) * 8;            // 0,8,16,24 (bf16 elements)

    unsigned sbase[3], dAh[3], dAl[3], dBh[3], dBl[3];
#pragma unroll
    for (int st = 0; st < 3; st++) {
        char* base = dynsm + st * STG_BYTES;
        sbase[st] = (unsigned)__cvta_generic_to_shared(base);
        unsigned ro = (arow * SMN + acol) * 2;
        dAh[st] = sbase[st] + ro;
        dAl[st] = sbase[st] + OFF_AL + ro;
        dBh[st] = sbase[st] + OFF_BH + ro;
        dBl[st] = sbase[st] + OFF_BL + ro;
    }
    const __nv_bfloat16* asrc_h = xh + (size_t)(m0 + arow) * KDIM + acol;
    const __nv_bfloat16* asrc_l = xl + (size_t)(m0 + arow) * KDIM + acol;
    const __nv_bfloat16* bsrc_h = g_Wh + (size_t)(n0 + arow) * KDIM + acol;
    const __nv_bfloat16* bsrc_l = g_Wl + (size_t)(n0 + arow) * KDIM + acol;

    float acc[2][2][4];
#pragma unroll
    for (int mb = 0; mb < 2; mb++)
#pragma unroll
        for (int nb = 0; nb < 2; nb++)
#pragma unroll
            for (int j = 0; j < 4; j++) acc[mb][nb][j] = 0.f;

#define ISSUE(s, st) do { \
    cp16(dAh[st], asrc_h + (s) * BK); \
    cp16(dAl[st], asrc_l + (s) * BK); \
    cp16(dBh[st], bsrc_h + (s) * BK); \
    cp16(dBl[st], bsrc_l + (s) * BK); \
    asm volatile("cp.async.commit_group;"); \
} while (0)

    ISSUE(0, 0);
    ISSUE(1, 1);

    int st = 0;  // stage buffer index for s
    for (int s = 0; s < NSTG; s++) {
        if (s < NSTG - 1) asm volatile("cp.async.wait_group 1;");
        else              asm volatile("cp.async.wait_group 0;");
        __syncthreads();   // data for stage s visible to all; buffer (s+2)%3 free
        if (s + 2 < NSTG) {
            int st2 = st + 2; if (st2 >= 3) st2 -= 3;
            ISSUE(s + 2, st2);
        }
        compute_stage(sbase[st], aoff, boff, acc);
        if (++st == 3) st = 0;
    }

    // Epilogue: even-qc lane holds (gi,gf), lane+1 holds (gg,go) of same hid.
#pragma unroll
    for (int mb = 0; mb < 2; mb++)
#pragma unroll
    for (int nb = 0; nb < 2; nb++) {
        float pg0 = __shfl_down_sync(0xffffffffu, acc[mb][nb][0], 1);
        float pg1 = __shfl_down_sync(0xffffffffu, acc[mb][nb][1], 1);
        float pg2 = __shfl_down_sync(0xffffffffu, acc[mb][nb][2], 1);
        float pg3 = __shfl_down_sync(0xffffffffu, acc[mb][nb][3], 1);
        if (!(qc & 1)) {
            int hid = ((n0 + wn) >> 2) + nb * 2 + (qc >> 1);
            float4 bb = *(const float4*)&g_bias[hid * 4];
            int g0 = m0 + wm + mb * 16 + qr;
            {
                float gi = acc[mb][nb][0] + bb.x, gf = acc[mb][nb][1] + bb.y;
                float gg = pg0 + bb.z,            go = pg1 + bb.w;
                float cold = g_c[g0 * DDIM + hid];
                float cn = fast_sig(gf) * cold + fast_sig(gi) * fast_tanh(gg);
                float hn = fast_sig(go) * fast_tanh(cn);
                g_c[g0 * DDIM + hid] = cn;
                hf[g0 * KDIM + hid]  = hn;                    // fp32 h (attn + output)
                __nv_bfloat16 hh = __float2bfloat16(hn);
                yh[g0 * KDIM + hid] = hh;                     // pre-split for next GEMM
                yl[g0 * KDIM + hid] = __float2bfloat16(hn - __bfloat162float(hh));
            }
            {
                int g1 = g0 + 8;
                float gi = acc[mb][nb][2] + bb.x, gf = acc[mb][nb][3] + bb.y;
                float gg = pg2 + bb.z,            go = pg3 + bb.w;
                float cold = g_c[g1 * DDIM + hid];
                float cn = fast_sig(gf) * cold + fast_sig(gi) * fast_tanh(gg);
                float hn = fast_sig(go) * fast_tanh(cn);
                g_c[g1 * DDIM + hid] = cn;
                hf[g1 * KDIM + hid]  = hn;
                __nv_bfloat16 hh = __float2bfloat16(hn);
                yh[g1 * KDIM + hid] = hh;
                yl[g1 * KDIM + hid] = __float2bfloat16(hn - __bfloat162float(hh));
            }
        }
    }
}

// ---------------------------------------------------------------------------
// Fused attention + readout, single pass over feat via BRANCHLESS online
// softmax with a running weighted vector, depth-1 prefetch.
// BOUSTROPHEDON: even iterations stream each segment forward, odd iterations
// backward -- the tail (resp. head) of each segment is still L2-resident from
// the previous pass (feat 205MB vs L2 126MB), so passes 2..6 get ~60% L2 hits.
// Online softmax is order-independent, so this is mathematically free.
// ---------------------------------------------------------------------------
__global__ void __launch_bounds__(256) attn_pass(const float* __restrict__ feat,
                                                 float* __restrict__ xf, int it) {
    __nv_bfloat16* yh = g_Xh[(it + 1) & 1];
    __nv_bfloat16* yl = g_Xl[(it + 1) & 1];

    int g    = blockIdx.x;
    int t    = threadIdx.x;
    int wid  = t >> 5;
    int lane = t & 31;

    const float* q = xf + g * KDIM;                // q = h just written by lstm_mma
    float4 qa = *(const float4*)&q[lane * 4];
    float4 qb = *(const float4*)&q[128 + lane * 4];

    int ns = g_segstart[g], ne = g_segstart[g + 1];
    int rem = ne - ns - wid;
    int cnt = (rem > 0) ? ((rem + 7) >> 3) : 0;    // nodes for this warp
    bool fwd = ((it & 1) == 0);
    int n    = fwd ? (ns + wid) : (ne - 1 - wid);
    int step = fwd ? 8 : -8;

    float m = -INFINITY, s = 0.f;
    float4 va = make_float4(0.f, 0.f, 0.f, 0.f);
    float4 vb = make_float4(0.f, 0.f, 0.f, 0.f);

    float4 c1 = make_float4(0.f, 0.f, 0.f, 0.f);
    float4 c2 = make_float4(0.f, 0.f, 0.f, 0.f);
    if (cnt > 0) {
        const float* f = feat + (size_t)n * DDIM;
        c1 = *(const float4*)&f[lane * 4];
        c2 = *(const float4*)&f[128 + lane * 4];
    }
    for (int j = 0; j < cnt; j++) {
        float4 p1 = make_float4(0.f, 0.f, 0.f, 0.f);
        float4 p2 = make_float4(0.f, 0.f, 0.f, 0.f);
        if (j + 1 < cnt) {                          // prefetch next node
            const float* f = feat + (size_t)(n + step) * DDIM;
            p1 = *(const float4*)&f[lane * 4];
            p2 = *(const float4*)&f[128 + lane * 4];
        }
        float e = c1.x * qa.x;
        e = fmaf(c1.y, qa.y, e); e = fmaf(c1.z, qa.z, e); e = fmaf(c1.w, qa.w, e);
        e = fmaf(c2.x, qb.x, e); e = fmaf(c2.y, qb.y, e);
        e = fmaf(c2.z, qb.z, e); e = fmaf(c2.w, qb.w, e);
        e += __shfl_xor_sync(0xffffffffu, e, 16);
        e += __shfl_xor_sync(0xffffffffu, e, 8);
        e += __shfl_xor_sync(0xffffffffu, e, 4);
        e += __shfl_xor_sync(0xffffffffu, e, 2);
        e += __shfl_xor_sync(0xffffffffu, e, 1);
        // branchless online-softmax update (exp(-inf)=0 covers first node)
        float mn = fmaxf(m, e);
        float sc = __expf(m - mn);
        float w  = __expf(e - mn);
        s = fmaf(s, sc, w);
        va.x = fmaf(va.x, sc, w * c1.x); va.y = fmaf(va.y, sc, w * c1.y);
        va.z = fmaf(va.z, sc, w * c1.z); va.w = fmaf(va.w, sc, w * c1.w);
        vb.x = fmaf(vb.x, sc, w * c2.x); vb.y = fmaf(vb.y, sc, w * c2.y);
        vb.z = fmaf(vb.z, sc, w * c2.z); vb.w = fmaf(vb.w, sc, w * c2.w);
        m = mn;
        c1 = p1; c2 = p2;
        n += step;
    }

    __shared__ float sm_m[8], sm_s[8];
    __shared__ float sm_v[8][256];
    if (lane == 0) { sm_m[wid] = m; sm_s[wid] = s; }
    *(float4*)&sm_v[wid][lane * 4]       = va;
    *(float4*)&sm_v[wid][128 + lane * 4] = vb;
    __syncthreads();

    // each thread finalizes one output dim
    float M = sm_m[0];
#pragma unroll
    for (int w = 1; w < 8; w++) M = fmaxf(M, sm_m[w]);
    float S = 0.f, val = 0.f;
#pragma unroll
    for (int w = 0; w < 8; w++) {
        float fw = (sm_s[w] > 0.f) ? __expf(sm_m[w] - M) : 0.f;  // guard empty warps
        S = fmaf(sm_s[w], fw, S);
        val = fmaf(sm_v[w][t], fw, val);
    }
    float r = (S > 0.f) ? val / S : 0.f;            // empty graph -> 0
    xf[g * KDIM + DDIM + t] = r;                    // fp32 (output at it=5)
    __nv_bfloat16 rh = __float2bfloat16(r);
    yh[g * KDIM + DDIM + t] = rh;                   // pre-split for next GEMM
    yl[g * KDIM + DDIM + t] = __float2bfloat16(r - __bfloat162float(rh));
}

// ---------------------------------------------------------------------------
// launch
// ---------------------------------------------------------------------------
extern "C" void kernel_launch(void* const* d_in, const int* in_sizes, int n_in,
                              void* d_out, int out_size) {
    const float* feat = (const float*)d_in[0];
    const float* W_ih = (const float*)d_in[1];
    const float* W_hh = (const float*)d_in[2];
    const float* b_ih = (const float*)d_in[3];
    const float* b_hh = (const float*)d_in[4];
    const int*   seg  = (const int*)d_in[5];
    int N = in_sizes[0] / DDIM;

    float* out = (float*)d_out;   // fp32 state buffer: layout == [h | readout] == q_star

    // opt-in to 60KB dynamic smem (idempotent attribute set, not an allocation)
    cudaFuncSetAttribute(lstm_mma, cudaFuncAttributeMaxDynamicSharedMemorySize,
                         3 * STG_BYTES);

    setup_fused<<<1024, 512>>>(W_ih, W_hh, b_ih, b_hh, seg, N);

    for (int it = 0; it < NITERS; it++) {
        lstm_mma<<<dim3(16, 16), 256, 3 * STG_BYTES>>>(out, it);
        attn_pass<<<BGRAPHS, 256>>>(feat, out, it);
    }
    // After it=5, out holds [h6 | readout6] = q_star.
}